// round 15
// baseline (speedup 1.0000x reference)
#include <cuda_runtime.h>
#include <math.h>
#include <stdint.h>

constexpr int B = 4, T = 4096, S = 4096, E = 16;
constexpr int NH = 16, H = 4, FFNH = 64;
constexpr int MD = 256, FF = 1024, OUT = 16;
constexpr int NTOK = B * T;
constexpr int GC = 16;                 // knn grid cells per axis
constexpr int NCG = 8;                 // fused-MLP column groups

// Scratch (static device allocations — no cudaMalloc allowed)
__device__ int    g_idx[NTOK * NH];                // 1 MB
__device__ float  g_oflat[(size_t)NTOK * MD];      // 16.8 MB (RNA-tf32 values)
__device__ float  g_w1r[MD * FF];                  // 1 MB  (RNA-tf32 W1)
__device__ float2 g_gxy[B][S];
__device__ int    g_gid[B][S];
__device__ int    g_cstart[B][GC * GC + 1];
__device__ float2 g_txy[B][T];                     // spatially-sorted targets
__device__ int    g_tid_[B][T];
__device__ float  g_partial[NCG][(size_t)NTOK * OUT];

__device__ __forceinline__ float gelu_exact(float x) {
    return 0.5f * x * (1.0f + erff(x * 0.70710678118654752f));
}

__device__ __forceinline__ float tf32_rna(float f) {
    uint32_t u;
    asm("cvt.rna.tf32.f32 %0, %1;" : "=r"(u) : "f"(f));
    return __uint_as_float(u);
}

__device__ __forceinline__ void cp_async16(uint32_t dst, const void* src) {
    asm volatile("cp.async.cg.shared.global [%0], [%1], 16;\n" :: "r"(dst), "l"(src));
}
__device__ __forceinline__ void cp_commit() {
    asm volatile("cp.async.commit_group;\n" ::);
}
__device__ __forceinline__ void cp_wait1() {
    asm volatile("cp.async.wait_group 1;\n" ::);
}

// ---------------------------------------------------------------------------
// K-1: pre-round W1 to RNA tf32.
// ---------------------------------------------------------------------------
__global__ __launch_bounds__(256) void w1_round(const float* __restrict__ W1) {
    const int i = blockIdx.x * 256 + threadIdx.x;
    g_w1r[i] = tf32_rna(W1[i]);
}

// ---------------------------------------------------------------------------
// K0a/K0b: counting-sort sources AND targets into the 16x16 grid.
// ---------------------------------------------------------------------------
__global__ __launch_bounds__(256) void grid_build(const float* __restrict__ cs) {
    __shared__ int cnt[GC * GC];
    __shared__ int start[GC * GC + 1];
    const int b = blockIdx.x, tid = threadIdx.x;
    cnt[tid] = 0;
    __syncthreads();
    const float2* csb = reinterpret_cast<const float2*>(cs) + (size_t)b * S;
    for (int i = tid; i < S; i += 256) {
        float2 c = csb[i];
        int cx = min(GC - 1, (int)(c.x * GC));
        int cy = min(GC - 1, (int)(c.y * GC));
        atomicAdd(&cnt[cy * GC + cx], 1);
    }
    __syncthreads();
    if (tid == 0) {
        int acc = 0;
        for (int i = 0; i < GC * GC; i++) { start[i] = acc; acc += cnt[i]; }
        start[GC * GC] = acc;
    }
    __syncthreads();
    cnt[tid] = start[tid];
    g_cstart[b][tid] = start[tid];
    if (tid == 0) g_cstart[b][GC * GC] = start[GC * GC];
    __syncthreads();
    for (int i = tid; i < S; i += 256) {
        float2 c = csb[i];
        int cx = min(GC - 1, (int)(c.x * GC));
        int cy = min(GC - 1, (int)(c.y * GC));
        int pos = atomicAdd(&cnt[cy * GC + cx], 1);
        g_gxy[b][pos] = c;
        g_gid[b][pos] = i;
    }
}

__global__ __launch_bounds__(256) void grid_build_t(const float* __restrict__ ct) {
    __shared__ int cnt[GC * GC];
    __shared__ int start[GC * GC + 1];
    const int b = blockIdx.x, tid = threadIdx.x;
    cnt[tid] = 0;
    __syncthreads();
    const float2* ctb = reinterpret_cast<const float2*>(ct) + (size_t)b * T;
    for (int i = tid; i < T; i += 256) {
        float2 c = ctb[i];
        int cx = min(GC - 1, (int)(c.x * GC));
        int cy = min(GC - 1, (int)(c.y * GC));
        atomicAdd(&cnt[cy * GC + cx], 1);
    }
    __syncthreads();
    if (tid == 0) {
        int acc = 0;
        for (int i = 0; i < GC * GC; i++) { start[i] = acc; acc += cnt[i]; }
        start[GC * GC] = acc;
    }
    __syncthreads();
    cnt[tid] = start[tid];
    __syncthreads();
    for (int i = tid; i < T; i += 256) {
        float2 c = ctb[i];
        int cx = min(GC - 1, (int)(c.x * GC));
        int cy = min(GC - 1, (int)(c.y * GC));
        int pos = atomicAdd(&cnt[cy * GC + cx], 1);
        g_txy[b][pos] = c;
        g_tid_[b][pos] = i;
    }
}

// ---------------------------------------------------------------------------
// K1: exact 16-NN, spatially-sorted targets, FOUR lanes per target.
// Cells partition by (ax&1)|((ay&1)<<1) (true partition; u64 keys make
// selection order-invariant). Merge: 2 snapshot-then-insert stages (xor1,
// xor2) — symmetric merges leave pair lanes identical between stages.
// Early stop: 4-lane min of local worsts (upper bound of union's 16th).
// ---------------------------------------------------------------------------
__device__ __forceinline__ void key_insert(unsigned long long* key,
                                           unsigned long long ck) {
    if (ck < key[NH - 1]) {
        bool ins = false;
#pragma unroll
        for (int q = 0; q < NH; q++) {
            bool sm = ins | (ck < key[q]);
            unsigned long long tk = key[q];
            key[q] = sm ? ck : tk;
            ck = sm ? tk : ck;
            ins = sm;
        }
    }
}

__global__ __launch_bounds__(256) void knn_kernel() {
    const int b = blockIdx.y;
    const int lane = threadIdx.x & 31;
    const int sub = threadIdx.x & 3;                     // cell class
    const unsigned quadmask = 0xFu << (lane & ~3);
    const int s = blockIdx.x * 64 + (threadIdx.x >> 2);  // sorted target slot
    const float2 tc = g_txy[b][s];
    const int torig = g_tid_[b][s];
    const float tx = tc.x, ty = tc.y;
    const int cx = min(GC - 1, (int)(tx * GC));
    const int cy = min(GC - 1, (int)(ty * GC));

    const float2* __restrict__ gxy = g_gxy[b];
    const int*    __restrict__ gid = g_gid[b];
    const int*    __restrict__ cst = g_cstart[b];
    constexpr float hcell = 1.0f / GC;
    constexpr unsigned long long KMAX = 0xFFFFFFFFFFFFFFFFull;

    unsigned long long key[NH];
#pragma unroll
    for (int i = 0; i < NH; i++) key[i] = KMAX;

    for (int rho = 0; rho <= GC - 1; rho++) {
        if (rho > 1) {
            float wl = __uint_as_float((unsigned)(key[NH - 1] >> 32));
            float w1 = fminf(wl, __shfl_xor_sync(quadmask, wl, 1));
            float wd2 = fminf(w1, __shfl_xor_sync(quadmask, w1, 2));
            const float bound = (rho - 1) * hcell;
            if (wd2 < bound * bound) break;              // uniform across quad
        }
        const int ylo = max(cy - rho, 0), yhi = min(cy + rho, GC - 1);
        for (int ay = ylo; ay <= yhi; ay++) {
            if ((ay & 1) != (sub >> 1)) continue;        // my y-parity class
            const bool fullrow = (ay == cy - rho) || (ay == cy + rho);
            const int step = fullrow ? 1 : (rho > 0 ? 2 * rho : 1);
            for (int ax = cx - rho; ax <= cx + rho; ax += step) {
                if (ax < 0 || ax >= GC) continue;
                if ((ax & 1) != (sub & 1)) continue;     // my x-parity class
                const int cell = ay * GC + ax;
                const int c1 = cst[cell + 1];
                for (int j = cst[cell]; j < c1; j++) {
                    const float2 p = gxy[j];
                    const float dxx = tx - p.x, dyy = ty - p.y;
                    const float d2 = fmaf(dyy, dyy, dxx * dxx);
                    unsigned long long ck =
                        ((unsigned long long)__float_as_uint(d2) << 32) |
                        (unsigned)gid[j];
                    key_insert(key, ck);
                }
            }
        }
    }

    // stage 1: merge xor-1 partner (snapshot first -> race-free)
    unsigned long long pk[NH];
#pragma unroll
    for (int i = 0; i < NH; i++)
        pk[i] = __shfl_xor_sync(quadmask, key[i], 1);
#pragma unroll
    for (int i = 0; i < NH; i++) key_insert(key, pk[i]);
    // stage 2: merge xor-2 partner
#pragma unroll
    for (int i = 0; i < NH; i++)
        pk[i] = __shfl_xor_sync(quadmask, key[i], 2);
#pragma unroll
    for (int i = 0; i < NH; i++) key_insert(key, pk[i]);

    if (sub == 0) {
        const int base = (b * T + torig) * NH;
#pragma unroll
        for (int i = 0; i < NH; i++)
            g_idx[base + i] = (int)(key[i] & 0xFFFFFFFFull);
    }
}

// ---------------------------------------------------------------------------
// K2: per-token pipeline (unchanged from R14, passing).
// ---------------------------------------------------------------------------
constexpr int O_PEW1 = 0;
constexpr int O_PEB1 = 128;
constexpr int O_PEW2 = 192;
constexpr int O_PEB2 = 1216;
constexpr int O_LNG  = 1232;
constexpr int O_LNB  = 1248;
constexpr int O_QW   = 1264;
constexpr int O_KW   = 1520;
constexpr int O_VW   = 1776;
constexpr int O_OW   = 2032;
constexpr int O_MW1  = 2288;
constexpr int O_MB1  = 3312;
constexpr int O_MW2  = 3376;
constexpr int O_MB2  = 3440;
constexpr int O_SC   = 3444;
constexpr int O_KV   = 3448;
constexpr int SM_TOT = 3448 + 16 * 132;

__device__ __forceinline__ void mat16(const float* __restrict__ Wsh,
                                      const float* __restrict__ vin,
                                      float* __restrict__ vout) {
#pragma unroll
    for (int k = 0; k < 16; k++) {
        const float hv = vin[k];
#pragma unroll
        for (int dq = 0; dq < 4; dq++) {
            float4 w = *reinterpret_cast<const float4*>(Wsh + k * 16 + dq * 4);
            vout[dq * 4 + 0] = fmaf(hv, w.x, vout[dq * 4 + 0]);
            vout[dq * 4 + 1] = fmaf(hv, w.y, vout[dq * 4 + 1]);
            vout[dq * 4 + 2] = fmaf(hv, w.z, vout[dq * 4 + 2]);
            vout[dq * 4 + 3] = fmaf(hv, w.w, vout[dq * 4 + 3]);
        }
    }
}

__global__ __launch_bounds__(256, 3) void token_kernel(
    const float* __restrict__ x, const float* __restrict__ ct, const float* __restrict__ cs,
    const float* __restrict__ pe_w1, const float* __restrict__ pe_b1,
    const float* __restrict__ pe_w2, const float* __restrict__ pe_b2,
    const float* __restrict__ ln_g, const float* __restrict__ ln_b,
    const float* __restrict__ q_w, const float* __restrict__ k_w,
    const float* __restrict__ v_w, const float* __restrict__ lscale,
    const float* __restrict__ out_w,
    const float* __restrict__ mnh_w1, const float* __restrict__ mnh_b1,
    const float* __restrict__ mnh_w2, const float* __restrict__ mnh_b2) {
    __shared__ float sm[SM_TOT];
    const int tid = threadIdx.x;
    for (int i = tid; i < 128;  i += 256) sm[O_PEW1 + i] = pe_w1[i];
    for (int i = tid; i < 64;   i += 256) sm[O_PEB1 + i] = pe_b1[i];
    for (int i = tid; i < 1024; i += 256) sm[O_PEW2 + i] = pe_w2[i];
    for (int i = tid; i < 16;   i += 256) sm[O_PEB2 + i] = pe_b2[i];
    for (int i = tid; i < 16;   i += 256) sm[O_LNG + i]  = ln_g[i];
    for (int i = tid; i < 16;   i += 256) sm[O_LNB + i]  = ln_b[i];
    for (int i = tid; i < 256;  i += 256) sm[O_QW + i]   = q_w[i];
    for (int i = tid; i < 256;  i += 256) sm[O_KW + i]   = k_w[i];
    for (int i = tid; i < 256;  i += 256) sm[O_VW + i]   = v_w[i];
    for (int i = tid; i < 256;  i += 256) sm[O_OW + i]   = out_w[i];
    for (int i = tid; i < 1024; i += 256) sm[O_MW1 + i]  = mnh_w1[i];
    for (int i = tid; i < 64;   i += 256) sm[O_MB1 + i]  = mnh_b1[i];
    for (int i = tid; i < 64;   i += 256) sm[O_MW2 + i]  = mnh_w2[i];
    if (tid == 0) sm[O_MB2] = mnh_b2[0];
    if (tid < 4)  sm[O_SC + tid] = expf(fminf(lscale[tid], 4.6051702f));
    __syncthreads();

    const int tok = blockIdx.x * 16 + (tid >> 4);
    const int g   = tid >> 4;
    const int i   = tid & 15;
    const int b   = tok / T;
    const int nidx = g_idx[tok * NH + i];

    float xr[16];
    const float4* xrow = reinterpret_cast<const float4*>(x + ((size_t)b * S + nidx) * E);
#pragma unroll
    for (int q4 = 0; q4 < 4; q4++) {
        float4 v4 = __ldg(xrow + q4);
        xr[q4 * 4 + 0] = v4.x; xr[q4 * 4 + 1] = v4.y;
        xr[q4 * 4 + 2] = v4.z; xr[q4 * 4 + 3] = v4.w;
    }
    const float2 scoord = __ldg(reinterpret_cast<const float2*>(cs) + (size_t)b * S + nidx);
    const float2 tcoord = __ldg(reinterpret_cast<const float2*>(ct) + tok);
    const float c0 = scoord.x - tcoord.x, c1 = scoord.y - tcoord.y;

    float h[16];
#pragma unroll
    for (int d = 0; d < 16; d++) h[d] = sm[O_PEB2 + d];
#pragma unroll
    for (int j4 = 0; j4 < FFNH; j4 += 4) {
        const float4 wa = *reinterpret_cast<const float4*>(sm + O_PEW1 + j4);
        const float4 wb = *reinterpret_cast<const float4*>(sm + O_PEW1 + 64 + j4);
        const float4 bb = *reinterpret_cast<const float4*>(sm + O_PEB1 + j4);
        float zq[4];
        zq[0] = fmaf(c0, wa.x, fmaf(c1, wb.x, bb.x));
        zq[1] = fmaf(c0, wa.y, fmaf(c1, wb.y, bb.y));
        zq[2] = fmaf(c0, wa.z, fmaf(c1, wb.z, bb.z));
        zq[3] = fmaf(c0, wa.w, fmaf(c1, wb.w, bb.w));
#pragma unroll
        for (int ss = 0; ss < 4; ss++) {
            const float z = gelu_exact(zq[ss]);
            const int j = j4 + ss;
#pragma unroll
            for (int dq = 0; dq < 4; dq++) {
                float4 w = *reinterpret_cast<const float4*>(sm + O_PEW2 + j * 16 + dq * 4);
                h[dq * 4 + 0] = fmaf(z, w.x, h[dq * 4 + 0]);
                h[dq * 4 + 1] = fmaf(z, w.y, h[dq * 4 + 1]);
                h[dq * 4 + 2] = fmaf(z, w.z, h[dq * 4 + 2]);
                h[dq * 4 + 3] = fmaf(z, w.w, h[dq * 4 + 3]);
            }
        }
    }

    float mu = 0.f;
#pragma unroll
    for (int d = 0; d < 16; d++) { h[d] += xr[d]; mu += h[d]; }
    mu *= (1.f / 16.f);
    float var = 0.f;
#pragma unroll
    for (int d = 0; d < 16; d++) { float c = h[d] - mu; var = fmaf(c, c, var); }
    var *= (1.f / 16.f);
    const float rstd = 1.f / sqrtf(var + 1e-5f);
#pragma unroll
    for (int d = 0; d < 16; d++)
        h[d] = (h[d] - mu) * rstd * sm[O_LNG + d] + sm[O_LNB + d];

    float q[16], k[16], v[16];
#pragma unroll
    for (int d = 0; d < 16; d++) { q[d] = 0.f; k[d] = 0.f; v[d] = 0.f; }
    mat16(sm + O_QW, h, q);
    mat16(sm + O_KW, h, k);
    mat16(sm + O_VW, xr, v);

    float4* myslot = reinterpret_cast<float4*>(sm + O_KV + g * 132 + i * 8);
    float o[16];
#pragma unroll
    for (int hh = 0; hh < H; hh++) {
        float qh[4], kh[4], vh[4];
#pragma unroll
        for (int c = 0; c < 4; c++) {
            qh[c] = q[hh * 4 + c]; kh[c] = k[hh * 4 + c]; vh[c] = v[hh * 4 + c];
        }
        float qs = fmaf(qh[3], qh[3], fmaf(qh[2], qh[2], fmaf(qh[1], qh[1], qh[0] * qh[0])));
        float ks = fmaf(kh[3], kh[3], fmaf(kh[2], kh[2], fmaf(kh[1], kh[1], kh[0] * kh[0])));
        const float qi = 1.f / (sqrtf(qs) + 1e-6f);
        const float ki = 1.f / (sqrtf(ks) + 1e-6f);
#pragma unroll
        for (int c = 0; c < 4; c++) { qh[c] *= qi; kh[c] *= ki; }

        __syncwarp();
        myslot[0] = make_float4(kh[0], kh[1], kh[2], kh[3]);
        myslot[1] = make_float4(vh[0], vh[1], vh[2], vh[3]);
        __syncwarp();

        const float scl = sm[O_SC + hh];
        float lg[16];
#pragma unroll
        for (int j = 0; j < 16; j++) {
            const float4 kj = *reinterpret_cast<const float4*>(sm + O_KV + g * 132 + j * 8);
            float dot = 0.f;
            dot = fmaf(qh[0], kj.x, dot);
            dot = fmaf(qh[1], kj.y, dot);
            dot = fmaf(qh[2], kj.z, dot);
            dot = fmaf(qh[3], kj.w, dot);
            lg[j] = dot * scl;
        }
        float mx = lg[0];
#pragma unroll
        for (int j = 1; j < 16; j++) mx = fmaxf(mx, lg[j]);
        float ssum = 0.f;
#pragma unroll
        for (int j = 0; j < 16; j++) { lg[j] = expf(lg[j] - mx); ssum += lg[j]; }
        const float inv = 1.f / ssum;
        float oh[4] = {0.f, 0.f, 0.f, 0.f};
#pragma unroll
        for (int j = 0; j < 16; j++) {
            const float a = lg[j] * inv;
            const float4 vj = *reinterpret_cast<const float4*>(sm + O_KV + g * 132 + j * 8 + 4);
            oh[0] = fmaf(a, vj.x, oh[0]);
            oh[1] = fmaf(a, vj.y, oh[1]);
            oh[2] = fmaf(a, vj.z, oh[2]);
            oh[3] = fmaf(a, vj.w, oh[3]);
        }
#pragma unroll
        for (int c = 0; c < 4; c++) o[hh * 4 + c] = oh[c];
    }

    float o2[16];
#pragma unroll
    for (int d = 0; d < 16; d++) o2[d] = 0.f;
    mat16(sm + O_OW, o, o2);

    float acc2 = 0.f;
#pragma unroll
    for (int jc = 0; jc < 4; jc++) {
        float z[16];
#pragma unroll
        for (int jq = 0; jq < 4; jq++) {
            const float4 bb = *reinterpret_cast<const float4*>(sm + O_MB1 + jc * 16 + jq * 4);
            z[jq * 4 + 0] = bb.x; z[jq * 4 + 1] = bb.y;
            z[jq * 4 + 2] = bb.z; z[jq * 4 + 3] = bb.w;
        }
#pragma unroll
        for (int kk = 0; kk < 16; kk++) {
            const float ov = o2[kk];
#pragma unroll
            for (int jq = 0; jq < 4; jq++) {
                const float4 w = *reinterpret_cast<const float4*>(
                    sm + O_MW1 + kk * 64 + jc * 16 + jq * 4);
                z[jq * 4 + 0] = fmaf(ov, w.x, z[jq * 4 + 0]);
                z[jq * 4 + 1] = fmaf(ov, w.y, z[jq * 4 + 1]);
                z[jq * 4 + 2] = fmaf(ov, w.z, z[jq * 4 + 2]);
                z[jq * 4 + 3] = fmaf(ov, w.w, z[jq * 4 + 3]);
            }
        }
#pragma unroll
        for (int j = 0; j < 16; j++)
            acc2 = fmaf(gelu_exact(z[j]), sm[O_MW2 + jc * 16 + j], acc2);
    }
    const float m = gelu_exact(acc2 + sm[O_MB2]);

    float4* dst = reinterpret_cast<float4*>(g_oflat + (size_t)tok * MD + i * 16);
#pragma unroll
    for (int dq = 0; dq < 4; dq++)
        dst[dq] = make_float4(tf32_rna(o2[dq * 4 + 0] + m), tf32_rna(o2[dq * 4 + 1] + m),
                              tf32_rna(o2[dq * 4 + 2] + m), tf32_rna(o2[dq * 4 + 3] + m));
}

// ---------------------------------------------------------------------------
// K3 (fused, RNA-tf32 operands staged via cp.async, double-buffered).
// ---------------------------------------------------------------------------
__device__ __forceinline__ void mma_tf32(float* c, const uint32_t* a, const uint32_t* bb) {
    asm volatile(
        "mma.sync.aligned.m16n8k8.row.col.f32.tf32.tf32.f32 "
        "{%0,%1,%2,%3}, {%4,%5,%6,%7}, {%8,%9}, {%0,%1,%2,%3};"
        : "+f"(c[0]), "+f"(c[1]), "+f"(c[2]), "+f"(c[3])
        : "r"(a[0]), "r"(a[1]), "r"(a[2]), "r"(a[3]), "r"(bb[0]), "r"(bb[1]));
}

constexpr int APAD = 36;
constexpr int BPAD = 72;
constexpr int CPAD = 66;
constexpr int BUFU = 128 * APAD + 32 * BPAD;       // 6912 floats per buffer
constexpr int FUSED_SMEM = 2 * BUFU * 4;           // 55296 B

__global__ __launch_bounds__(256) void fused_mlp_kernel(
    const float* __restrict__ b1, const float* __restrict__ W2) {
    extern __shared__ __align__(16) uint32_t smem_u[];
    float* Cs  = reinterpret_cast<float*>(smem_u);
    float* W2s = reinterpret_cast<float*>(smem_u) + 128 * CPAD;
    const uint32_t smem_base = (uint32_t)__cvta_generic_to_shared(smem_u);

    const int tid  = threadIdx.x;
    const int lane = tid & 31;
    const int wid  = tid >> 5;
    const int warp_m = wid & 3;
    const int warp_n = wid >> 2;
    const int row0 = blockIdx.x * 128;
    const int cg   = blockIdx.y;

    const int a_row  = tid >> 1;
    const int a_kofs = (tid & 1) * 16;
    const int b_krow = tid >> 3;
    const int b_ncol = (tid & 7) * 8;
    const int p2row = tid >> 1;
    const int p2n   = (tid & 1) * 8;

    const float* arow_g = g_oflat + (size_t)(row0 + a_row) * MD + a_kofs;
    const uint32_t a_dst = (uint32_t)(a_row * APAD + a_kofs) * 4u;
    const uint32_t b_dst = (uint32_t)(128 * APAD + b_krow * BPAD + b_ncol) * 4u;

    float out_acc[8];
#pragma unroll
    for (int i = 0; i < 8; i++) out_acc[i] = 0.f;

    for (int ch = cg * 2; ch < cg * 2 + 2; ch++) {
        const int col0 = ch * 64;
        const float* brow_g = g_w1r + (size_t)b_krow * FF + col0 + b_ncol;
        float cfr[2][4][4];
#pragma unroll
        for (int ma = 0; ma < 2; ma++)
#pragma unroll
            for (int na = 0; na < 4; na++)
#pragma unroll
                for (int i = 0; i < 4; i++) cfr[ma][na][i] = 0.f;

        {
            const uint32_t base = smem_base;
#pragma unroll
            for (int q = 0; q < 4; q++)
                cp_async16(base + a_dst + q * 16, arow_g + q * 4);
#pragma unroll
            for (int q = 0; q < 2; q++)
                cp_async16(base + b_dst + q * 16, brow_g + q * 4);
            cp_commit();
        }

#pragma unroll 1
        for (int kt = 0; kt < 8; kt++) {
            __syncthreads();
            if (kt < 7) {
                const uint32_t base = smem_base + (uint32_t)(((kt + 1) & 1) * BUFU) * 4u;
                const float* ag = arow_g + (kt + 1) * 32;
                const float* bg = brow_g + (size_t)(kt + 1) * 32 * FF;
#pragma unroll
                for (int q = 0; q < 4; q++)
                    cp_async16(base + a_dst + q * 16, ag + q * 4);
#pragma unroll
                for (int q = 0; q < 2; q++)
                    cp_async16(base + b_dst + q * 16, bg + q * 4);
            }
            cp_commit();
            cp_wait1();
            __syncthreads();

            const uint32_t* As = smem_u + (kt & 1) * BUFU;
            const uint32_t* Bs = As + 128 * APAD;
#pragma unroll
            for (int ks = 0; ks < 4; ks++) {
                const int k0 = ks * 8;
                uint32_t afr[2][4];
#pragma unroll
                for (int ma = 0; ma < 2; ma++) {
                    const int r = warp_m * 32 + ma * 16 + (lane >> 2);
                    const int kc = k0 + (lane & 3);
                    afr[ma][0] = As[r * APAD + kc];
                    afr[ma][1] = As[(r + 8) * APAD + kc];
                    afr[ma][2] = As[r * APAD + kc + 4];
                    afr[ma][3] = As[(r + 8) * APAD + kc + 4];
                }
                uint32_t bfr[4][2];
#pragma unroll
                for (int na = 0; na < 4; na++) {
                    const int n = warp_n * 32 + na * 8 + (lane >> 2);
                    const int kc = k0 + (lane & 3);
                    bfr[na][0] = Bs[kc * BPAD + n];
                    bfr[na][1] = Bs[(kc + 4) * BPAD + n];
                }
#pragma unroll
                for (int ma = 0; ma < 2; ma++)
#pragma unroll
                    for (int na = 0; na < 4; na++)
                        mma_tf32(cfr[ma][na], afr[ma], bfr[na]);
            }
        }

        __syncthreads();

#pragma unroll
        for (int ma = 0; ma < 2; ma++) {
            const int r0 = warp_m * 32 + ma * 16 + (lane >> 2);
#pragma unroll
            for (int na = 0; na < 4; na++) {
                const int cl = warp_n * 32 + na * 8 + 2 * (lane & 3);
                const float bb0 = __ldg(b1 + col0 + cl);
                const float bb1 = __ldg(b1 + col0 + cl + 1);
                float2 v0, v1;
                v0.x = gelu_exact(cfr[ma][na][0] + bb0);
                v0.y = gelu_exact(cfr[ma][na][1] + bb1);
                v1.x = gelu_exact(cfr[ma][na][2] + bb0);
                v1.y = gelu_exact(cfr[ma][na][3] + bb1);
                *reinterpret_cast<float2*>(&Cs[r0 * CPAD + cl]) = v0;
                *reinterpret_cast<float2*>(&Cs[(r0 + 8) * CPAD + cl]) = v1;
            }
        }
        *reinterpret_cast<float4*>(&W2s[(tid >> 2) * 16 + (tid & 3) * 4]) =
            *reinterpret_cast<const float4*>(W2 + (size_t)(col0 + (tid >> 2)) * 16 + (tid & 3) * 4);
        __syncthreads();

#pragma unroll 8
        for (int c = 0; c < 64; c++) {
            const float cv = Cs[p2row * CPAD + c];
            const float4 wa = *reinterpret_cast<const float4*>(&W2s[c * 16 + p2n]);
            const float4 wb = *reinterpret_cast<const float4*>(&W2s[c * 16 + p2n + 4]);
            out_acc[0] = fmaf(cv, wa.x, out_acc[0]);
            out_acc[1] = fmaf(cv, wa.y, out_acc[1]);
            out_acc[2] = fmaf(cv, wa.z, out_acc[2]);
            out_acc[3] = fmaf(cv, wa.w, out_acc[3]);
            out_acc[4] = fmaf(cv, wb.x, out_acc[4]);
            out_acc[5] = fmaf(cv, wb.y, out_acc[5]);
            out_acc[6] = fmaf(cv, wb.z, out_acc[6]);
            out_acc[7] = fmaf(cv, wb.w, out_acc[7]);
        }
        __syncthreads();
    }

    float* prow = &g_partial[cg][(size_t)(row0 + p2row) * OUT + p2n];
    *reinterpret_cast<float4*>(prow)     = make_float4(out_acc[0], out_acc[1], out_acc[2], out_acc[3]);
    *reinterpret_cast<float4*>(prow + 4) = make_float4(out_acc[4], out_acc[5], out_acc[6], out_acc[7]);
}

// ---------------------------------------------------------------------------
// K4: out = gelu(sum_cg partial + b2). Fixed summation order -> deterministic.
// ---------------------------------------------------------------------------
__global__ __launch_bounds__(256) void out_reduce(const float* __restrict__ b2,
                                                  float* __restrict__ out) {
    const int gid = blockIdx.x * 256 + threadIdx.x;
    const int n = gid & (OUT - 1);
    float s = g_partial[0][gid];
#pragma unroll
    for (int cg = 1; cg < NCG; cg++) s += g_partial[cg][gid];
    out[gid] = gelu_exact(s + b2[n]);
}

// ---------------------------------------------------------------------------
extern "C" void kernel_launch(void* const* d_in, const int* in_sizes, int n_in,
                              void* d_out, int out_size) {
    const float* x      = (const float*)d_in[0];
    const float* ct     = (const float*)d_in[1];
    const float* cs     = (const float*)d_in[2];
    const float* pe_w1  = (const float*)d_in[3];
    const float* pe_b1  = (const float*)d_in[4];
    const float* pe_w2  = (const float*)d_in[5];
    const float* pe_b2  = (const float*)d_in[6];
    const float* ln_g   = (const float*)d_in[7];
    const float* ln_b   = (const float*)d_in[8];
    const float* q_w    = (const float*)d_in[9];
    const float* k_w    = (const float*)d_in[10];
    const float* v_w    = (const float*)d_in[11];
    const float* ls     = (const float*)d_in[12];
    const float* out_w  = (const float*)d_in[13];
    const float* mnh_w1 = (const float*)d_in[14];
    const float* mnh_b1 = (const float*)d_in[15];
    const float* mnh_w2 = (const float*)d_in[16];
    const float* mnh_b2 = (const float*)d_in[17];
    const float* mo_w1  = (const float*)d_in[18];
    const float* mo_b1  = (const float*)d_in[19];
    const float* mo_w2  = (const float*)d_in[20];
    const float* mo_b2  = (const float*)d_in[21];

    cudaFuncSetAttribute(fused_mlp_kernel,
                         cudaFuncAttributeMaxDynamicSharedMemorySize, FUSED_SMEM);

    w1_round<<<MD * FF / 256, 256>>>(mo_w1);
    grid_build<<<B, 256>>>(cs);
    grid_build_t<<<B, 256>>>(ct);
    knn_kernel<<<dim3(T / 64, B), 256>>>();
    token_kernel<<<NTOK / 16, 256>>>(x, ct, cs, pe_w1, pe_b1, pe_w2, pe_b2,
                                     ln_g, ln_b, q_w, k_w, v_w, ls, out_w,
                                     mnh_w1, mnh_b1, mnh_w2, mnh_b2);
    fused_mlp_kernel<<<dim3(NTOK / 128, NCG), 256, FUSED_SMEM>>>(mo_b1, mo_w2);
    out_reduce<<<NTOK * OUT / 256, 256>>>(mo_b2, (float*)d_out);
}

// round 16
// speedup vs baseline: 1.1975x; 1.1975x over previous
#include <cuda_runtime.h>
#include <math.h>
#include <stdint.h>

constexpr int B = 4, T = 4096, S = 4096, E = 16;
constexpr int NH = 16, H = 4, FFNH = 64;
constexpr int MD = 256, FF = 1024, OUT = 16;
constexpr int NTOK = B * T;
constexpr int GC = 16;                 // knn grid cells per axis
constexpr int NCG = 8;                 // fused-MLP column groups

// Scratch (static device allocations — no cudaMalloc allowed)
__device__ int    g_idx[NTOK * NH];                // 1 MB
__device__ float  g_oflat[(size_t)NTOK * MD];      // 16.8 MB (RNA-tf32 values)
__device__ float  g_w1r[MD * FF];                  // 1 MB  (RNA-tf32 W1)
__device__ float2 g_gxy[B][S];
__device__ int    g_gid[B][S];
__device__ int    g_cstart[B][GC * GC + 1];
__device__ float2 g_txy[B][T];                     // spatially-sorted targets
__device__ int    g_tid_[B][T];
__device__ float  g_partial[NCG][(size_t)NTOK * OUT];

__device__ __forceinline__ float gelu_exact(float x) {
    return 0.5f * x * (1.0f + erff(x * 0.70710678118654752f));
}

__device__ __forceinline__ float tf32_rna(float f) {
    uint32_t u;
    asm("cvt.rna.tf32.f32 %0, %1;" : "=r"(u) : "f"(f));
    return __uint_as_float(u);
}

__device__ __forceinline__ void cp_async16(uint32_t dst, const void* src) {
    asm volatile("cp.async.cg.shared.global [%0], [%1], 16;\n" :: "r"(dst), "l"(src));
}
__device__ __forceinline__ void cp_commit() {
    asm volatile("cp.async.commit_group;\n" ::);
}
__device__ __forceinline__ void cp_wait1() {
    asm volatile("cp.async.wait_group 1;\n" ::);
}

// ---------------------------------------------------------------------------
// K-1: pre-round W1 to RNA tf32.
// ---------------------------------------------------------------------------
__global__ __launch_bounds__(256) void w1_round(const float* __restrict__ W1) {
    const int i = blockIdx.x * 256 + threadIdx.x;
    g_w1r[i] = tf32_rna(W1[i]);
}

// ---------------------------------------------------------------------------
// K0a/K0b: counting-sort sources AND targets into the 16x16 grid.
// ---------------------------------------------------------------------------
__global__ __launch_bounds__(256) void grid_build(const float* __restrict__ cs) {
    __shared__ int cnt[GC * GC];
    __shared__ int start[GC * GC + 1];
    const int b = blockIdx.x, tid = threadIdx.x;
    cnt[tid] = 0;
    __syncthreads();
    const float2* csb = reinterpret_cast<const float2*>(cs) + (size_t)b * S;
    for (int i = tid; i < S; i += 256) {
        float2 c = csb[i];
        int cx = min(GC - 1, (int)(c.x * GC));
        int cy = min(GC - 1, (int)(c.y * GC));
        atomicAdd(&cnt[cy * GC + cx], 1);
    }
    __syncthreads();
    if (tid == 0) {
        int acc = 0;
        for (int i = 0; i < GC * GC; i++) { start[i] = acc; acc += cnt[i]; }
        start[GC * GC] = acc;
    }
    __syncthreads();
    cnt[tid] = start[tid];
    g_cstart[b][tid] = start[tid];
    if (tid == 0) g_cstart[b][GC * GC] = start[GC * GC];
    __syncthreads();
    for (int i = tid; i < S; i += 256) {
        float2 c = csb[i];
        int cx = min(GC - 1, (int)(c.x * GC));
        int cy = min(GC - 1, (int)(c.y * GC));
        int pos = atomicAdd(&cnt[cy * GC + cx], 1);
        g_gxy[b][pos] = c;
        g_gid[b][pos] = i;
    }
}

__global__ __launch_bounds__(256) void grid_build_t(const float* __restrict__ ct) {
    __shared__ int cnt[GC * GC];
    __shared__ int start[GC * GC + 1];
    const int b = blockIdx.x, tid = threadIdx.x;
    cnt[tid] = 0;
    __syncthreads();
    const float2* ctb = reinterpret_cast<const float2*>(ct) + (size_t)b * T;
    for (int i = tid; i < T; i += 256) {
        float2 c = ctb[i];
        int cx = min(GC - 1, (int)(c.x * GC));
        int cy = min(GC - 1, (int)(c.y * GC));
        atomicAdd(&cnt[cy * GC + cx], 1);
    }
    __syncthreads();
    if (tid == 0) {
        int acc = 0;
        for (int i = 0; i < GC * GC; i++) { start[i] = acc; acc += cnt[i]; }
        start[GC * GC] = acc;
    }
    __syncthreads();
    cnt[tid] = start[tid];
    __syncthreads();
    for (int i = tid; i < T; i += 256) {
        float2 c = ctb[i];
        int cx = min(GC - 1, (int)(c.x * GC));
        int cy = min(GC - 1, (int)(c.y * GC));
        int pos = atomicAdd(&cnt[cy * GC + cx], 1);
        g_txy[b][pos] = c;
        g_tid_[b][pos] = i;
    }
}

// ---------------------------------------------------------------------------
// K1: exact 16-NN, spatially-sorted targets, EIGHT lanes per target.
// All lanes walk the same cells; each cell's POINTS split j += 8 (balanced).
// Merge: 3 stages of bitonic set-merge: t[i]=min(A[i],B[15-i]) is provably
// the 16 smallest of the union (bitonic), then a 4-stage half-cleaner sorts.
// u64 (d2,idx) keys -> order-invariant, identical output to insertion merge.
// ---------------------------------------------------------------------------
__device__ __forceinline__ void key_insert(unsigned long long* key,
                                           unsigned long long ck) {
    if (ck < key[NH - 1]) {
        bool ins = false;
#pragma unroll
        for (int q = 0; q < NH; q++) {
            bool sm = ins | (ck < key[q]);
            unsigned long long tk = key[q];
            key[q] = sm ? ck : tk;
            ck = sm ? tk : ck;
            ins = sm;
        }
    }
}

__global__ __launch_bounds__(256) void knn_kernel() {
    const int b = blockIdx.y;
    const int lane = threadIdx.x & 31;
    const int sub = threadIdx.x & 7;                     // point-split class
    const unsigned octmask = 0xFFu << (lane & ~7);
    const int s = blockIdx.x * 32 + (threadIdx.x >> 3);  // sorted target slot
    const float2 tc = g_txy[b][s];
    const int torig = g_tid_[b][s];
    const float tx = tc.x, ty = tc.y;
    const int cx = min(GC - 1, (int)(tx * GC));
    const int cy = min(GC - 1, (int)(ty * GC));

    const float2* __restrict__ gxy = g_gxy[b];
    const int*    __restrict__ gid = g_gid[b];
    const int*    __restrict__ cst = g_cstart[b];
    constexpr float hcell = 1.0f / GC;
    constexpr unsigned long long KMAX = 0xFFFFFFFFFFFFFFFFull;

    unsigned long long key[NH];
#pragma unroll
    for (int i = 0; i < NH; i++) key[i] = KMAX;

    for (int rho = 0; rho <= GC - 1; rho++) {
        if (rho > 1) {
            // min of local worsts over the octet: upper-bounds union's 16th.
            // fminf is NaN-safe (lane with <16 found contributes NaN -> skipped;
            // all-NaN -> no exit).
            float wl = __uint_as_float((unsigned)(key[NH - 1] >> 32));
            wl = fminf(wl, __shfl_xor_sync(octmask, wl, 1));
            wl = fminf(wl, __shfl_xor_sync(octmask, wl, 2));
            wl = fminf(wl, __shfl_xor_sync(octmask, wl, 4));
            const float bound = (rho - 1) * hcell;
            if (wl < bound * bound) break;               // uniform across octet
        }
        const int ylo = max(cy - rho, 0), yhi = min(cy + rho, GC - 1);
        for (int ay = ylo; ay <= yhi; ay++) {
            const bool fullrow = (ay == cy - rho) || (ay == cy + rho);
            const int step = fullrow ? 1 : (rho > 0 ? 2 * rho : 1);
            for (int ax = cx - rho; ax <= cx + rho; ax += step) {
                if (ax < 0 || ax >= GC) continue;
                const int cell = ay * GC + ax;
                const int c1 = cst[cell + 1];
                for (int j = cst[cell] + sub; j < c1; j += 8) {
                    const float2 p = gxy[j];
                    const float dxx = tx - p.x, dyy = ty - p.y;
                    const float d2 = fmaf(dyy, dyy, dxx * dxx);
                    unsigned long long ck =
                        ((unsigned long long)__float_as_uint(d2) << 32) |
                        (unsigned)gid[j];
                    key_insert(key, ck);
                }
            }
        }
    }

    // 3 merge stages: xor 1, 2, 4. Each stage: shuffle partner's key[15-i]
    // (reads current regs; writes go to tmp -> race-free), take mins, sort.
#pragma unroll
    for (int st = 0; st < 3; st++) {
        const int d = 1 << st;
        unsigned long long t[NH];
#pragma unroll
        for (int i = 0; i < NH; i++) {
            unsigned long long other = __shfl_xor_sync(octmask, key[NH - 1 - i], d);
            t[i] = key[i] < other ? key[i] : other;
        }
        // bitonic half-cleaner sort (input bitonic, output ascending)
#pragma unroll
        for (int dd = 8; dd >= 1; dd >>= 1) {
#pragma unroll
            for (int i = 0; i < NH; i++) {
                if (!(i & dd)) {
                    unsigned long long a = t[i], bb = t[i | dd];
                    t[i]      = a < bb ? a : bb;
                    t[i | dd] = a < bb ? bb : a;
                }
            }
        }
#pragma unroll
        for (int i = 0; i < NH; i++) key[i] = t[i];
    }

    if (sub == 0) {
        const int base = (b * T + torig) * NH;
#pragma unroll
        for (int i = 0; i < NH; i++)
            g_idx[base + i] = (int)(key[i] & 0xFFFFFFFFull);
    }
}

// ---------------------------------------------------------------------------
// K2: per-token pipeline (unchanged from R14, passing).
// ---------------------------------------------------------------------------
constexpr int O_PEW1 = 0;
constexpr int O_PEB1 = 128;
constexpr int O_PEW2 = 192;
constexpr int O_PEB2 = 1216;
constexpr int O_LNG  = 1232;
constexpr int O_LNB  = 1248;
constexpr int O_QW   = 1264;
constexpr int O_KW   = 1520;
constexpr int O_VW   = 1776;
constexpr int O_OW   = 2032;
constexpr int O_MW1  = 2288;
constexpr int O_MB1  = 3312;
constexpr int O_MW2  = 3376;
constexpr int O_MB2  = 3440;
constexpr int O_SC   = 3444;
constexpr int O_KV   = 3448;
constexpr int SM_TOT = 3448 + 16 * 132;

__device__ __forceinline__ void mat16(const float* __restrict__ Wsh,
                                      const float* __restrict__ vin,
                                      float* __restrict__ vout) {
#pragma unroll
    for (int k = 0; k < 16; k++) {
        const float hv = vin[k];
#pragma unroll
        for (int dq = 0; dq < 4; dq++) {
            float4 w = *reinterpret_cast<const float4*>(Wsh + k * 16 + dq * 4);
            vout[dq * 4 + 0] = fmaf(hv, w.x, vout[dq * 4 + 0]);
            vout[dq * 4 + 1] = fmaf(hv, w.y, vout[dq * 4 + 1]);
            vout[dq * 4 + 2] = fmaf(hv, w.z, vout[dq * 4 + 2]);
            vout[dq * 4 + 3] = fmaf(hv, w.w, vout[dq * 4 + 3]);
        }
    }
}

__global__ __launch_bounds__(256, 3) void token_kernel(
    const float* __restrict__ x, const float* __restrict__ ct, const float* __restrict__ cs,
    const float* __restrict__ pe_w1, const float* __restrict__ pe_b1,
    const float* __restrict__ pe_w2, const float* __restrict__ pe_b2,
    const float* __restrict__ ln_g, const float* __restrict__ ln_b,
    const float* __restrict__ q_w, const float* __restrict__ k_w,
    const float* __restrict__ v_w, const float* __restrict__ lscale,
    const float* __restrict__ out_w,
    const float* __restrict__ mnh_w1, const float* __restrict__ mnh_b1,
    const float* __restrict__ mnh_w2, const float* __restrict__ mnh_b2) {
    __shared__ float sm[SM_TOT];
    const int tid = threadIdx.x;
    for (int i = tid; i < 128;  i += 256) sm[O_PEW1 + i] = pe_w1[i];
    for (int i = tid; i < 64;   i += 256) sm[O_PEB1 + i] = pe_b1[i];
    for (int i = tid; i < 1024; i += 256) sm[O_PEW2 + i] = pe_w2[i];
    for (int i = tid; i < 16;   i += 256) sm[O_PEB2 + i] = pe_b2[i];
    for (int i = tid; i < 16;   i += 256) sm[O_LNG + i]  = ln_g[i];
    for (int i = tid; i < 16;   i += 256) sm[O_LNB + i]  = ln_b[i];
    for (int i = tid; i < 256;  i += 256) sm[O_QW + i]   = q_w[i];
    for (int i = tid; i < 256;  i += 256) sm[O_KW + i]   = k_w[i];
    for (int i = tid; i < 256;  i += 256) sm[O_VW + i]   = v_w[i];
    for (int i = tid; i < 256;  i += 256) sm[O_OW + i]   = out_w[i];
    for (int i = tid; i < 1024; i += 256) sm[O_MW1 + i]  = mnh_w1[i];
    for (int i = tid; i < 64;   i += 256) sm[O_MB1 + i]  = mnh_b1[i];
    for (int i = tid; i < 64;   i += 256) sm[O_MW2 + i]  = mnh_w2[i];
    if (tid == 0) sm[O_MB2] = mnh_b2[0];
    if (tid < 4)  sm[O_SC + tid] = expf(fminf(lscale[tid], 4.6051702f));
    __syncthreads();

    const int tok = blockIdx.x * 16 + (tid >> 4);
    const int g   = tid >> 4;
    const int i   = tid & 15;
    const int b   = tok / T;
    const int nidx = g_idx[tok * NH + i];

    float xr[16];
    const float4* xrow = reinterpret_cast<const float4*>(x + ((size_t)b * S + nidx) * E);
#pragma unroll
    for (int q4 = 0; q4 < 4; q4++) {
        float4 v4 = __ldg(xrow + q4);
        xr[q4 * 4 + 0] = v4.x; xr[q4 * 4 + 1] = v4.y;
        xr[q4 * 4 + 2] = v4.z; xr[q4 * 4 + 3] = v4.w;
    }
    const float2 scoord = __ldg(reinterpret_cast<const float2*>(cs) + (size_t)b * S + nidx);
    const float2 tcoord = __ldg(reinterpret_cast<const float2*>(ct) + tok);
    const float c0 = scoord.x - tcoord.x, c1 = scoord.y - tcoord.y;

    float h[16];
#pragma unroll
    for (int d = 0; d < 16; d++) h[d] = sm[O_PEB2 + d];
#pragma unroll
    for (int j4 = 0; j4 < FFNH; j4 += 4) {
        const float4 wa = *reinterpret_cast<const float4*>(sm + O_PEW1 + j4);
        const float4 wb = *reinterpret_cast<const float4*>(sm + O_PEW1 + 64 + j4);
        const float4 bb = *reinterpret_cast<const float4*>(sm + O_PEB1 + j4);
        float zq[4];
        zq[0] = fmaf(c0, wa.x, fmaf(c1, wb.x, bb.x));
        zq[1] = fmaf(c0, wa.y, fmaf(c1, wb.y, bb.y));
        zq[2] = fmaf(c0, wa.z, fmaf(c1, wb.z, bb.z));
        zq[3] = fmaf(c0, wa.w, fmaf(c1, wb.w, bb.w));
#pragma unroll
        for (int ss = 0; ss < 4; ss++) {
            const float z = gelu_exact(zq[ss]);
            const int j = j4 + ss;
#pragma unroll
            for (int dq = 0; dq < 4; dq++) {
                float4 w = *reinterpret_cast<const float4*>(sm + O_PEW2 + j * 16 + dq * 4);
                h[dq * 4 + 0] = fmaf(z, w.x, h[dq * 4 + 0]);
                h[dq * 4 + 1] = fmaf(z, w.y, h[dq * 4 + 1]);
                h[dq * 4 + 2] = fmaf(z, w.z, h[dq * 4 + 2]);
                h[dq * 4 + 3] = fmaf(z, w.w, h[dq * 4 + 3]);
            }
        }
    }

    float mu = 0.f;
#pragma unroll
    for (int d = 0; d < 16; d++) { h[d] += xr[d]; mu += h[d]; }
    mu *= (1.f / 16.f);
    float var = 0.f;
#pragma unroll
    for (int d = 0; d < 16; d++) { float c = h[d] - mu; var = fmaf(c, c, var); }
    var *= (1.f / 16.f);
    const float rstd = 1.f / sqrtf(var + 1e-5f);
#pragma unroll
    for (int d = 0; d < 16; d++)
        h[d] = (h[d] - mu) * rstd * sm[O_LNG + d] + sm[O_LNB + d];

    float q[16], k[16], v[16];
#pragma unroll
    for (int d = 0; d < 16; d++) { q[d] = 0.f; k[d] = 0.f; v[d] = 0.f; }
    mat16(sm + O_QW, h, q);
    mat16(sm + O_KW, h, k);
    mat16(sm + O_VW, xr, v);

    float4* myslot = reinterpret_cast<float4*>(sm + O_KV + g * 132 + i * 8);
    float o[16];
#pragma unroll
    for (int hh = 0; hh < H; hh++) {
        float qh[4], kh[4], vh[4];
#pragma unroll
        for (int c = 0; c < 4; c++) {
            qh[c] = q[hh * 4 + c]; kh[c] = k[hh * 4 + c]; vh[c] = v[hh * 4 + c];
        }
        float qs = fmaf(qh[3], qh[3], fmaf(qh[2], qh[2], fmaf(qh[1], qh[1], qh[0] * qh[0])));
        float ks = fmaf(kh[3], kh[3], fmaf(kh[2], kh[2], fmaf(kh[1], kh[1], kh[0] * kh[0])));
        const float qi = 1.f / (sqrtf(qs) + 1e-6f);
        const float ki = 1.f / (sqrtf(ks) + 1e-6f);
#pragma unroll
        for (int c = 0; c < 4; c++) { qh[c] *= qi; kh[c] *= ki; }

        __syncwarp();
        myslot[0] = make_float4(kh[0], kh[1], kh[2], kh[3]);
        myslot[1] = make_float4(vh[0], vh[1], vh[2], vh[3]);
        __syncwarp();

        const float scl = sm[O_SC + hh];
        float lg[16];
#pragma unroll
        for (int j = 0; j < 16; j++) {
            const float4 kj = *reinterpret_cast<const float4*>(sm + O_KV + g * 132 + j * 8);
            float dot = 0.f;
            dot = fmaf(qh[0], kj.x, dot);
            dot = fmaf(qh[1], kj.y, dot);
            dot = fmaf(qh[2], kj.z, dot);
            dot = fmaf(qh[3], kj.w, dot);
            lg[j] = dot * scl;
        }
        float mx = lg[0];
#pragma unroll
        for (int j = 1; j < 16; j++) mx = fmaxf(mx, lg[j]);
        float ssum = 0.f;
#pragma unroll
        for (int j = 0; j < 16; j++) { lg[j] = expf(lg[j] - mx); ssum += lg[j]; }
        const float inv = 1.f / ssum;
        float oh[4] = {0.f, 0.f, 0.f, 0.f};
#pragma unroll
        for (int j = 0; j < 16; j++) {
            const float a = lg[j] * inv;
            const float4 vj = *reinterpret_cast<const float4*>(sm + O_KV + g * 132 + j * 8 + 4);
            oh[0] = fmaf(a, vj.x, oh[0]);
            oh[1] = fmaf(a, vj.y, oh[1]);
            oh[2] = fmaf(a, vj.z, oh[2]);
            oh[3] = fmaf(a, vj.w, oh[3]);
        }
#pragma unroll
        for (int c = 0; c < 4; c++) o[hh * 4 + c] = oh[c];
    }

    float o2[16];
#pragma unroll
    for (int d = 0; d < 16; d++) o2[d] = 0.f;
    mat16(sm + O_OW, o, o2);

    float acc2 = 0.f;
#pragma unroll
    for (int jc = 0; jc < 4; jc++) {
        float z[16];
#pragma unroll
        for (int jq = 0; jq < 4; jq++) {
            const float4 bb = *reinterpret_cast<const float4*>(sm + O_MB1 + jc * 16 + jq * 4);
            z[jq * 4 + 0] = bb.x; z[jq * 4 + 1] = bb.y;
            z[jq * 4 + 2] = bb.z; z[jq * 4 + 3] = bb.w;
        }
#pragma unroll
        for (int kk = 0; kk < 16; kk++) {
            const float ov = o2[kk];
#pragma unroll
            for (int jq = 0; jq < 4; jq++) {
                const float4 w = *reinterpret_cast<const float4*>(
                    sm + O_MW1 + kk * 64 + jc * 16 + jq * 4);
                z[jq * 4 + 0] = fmaf(ov, w.x, z[jq * 4 + 0]);
                z[jq * 4 + 1] = fmaf(ov, w.y, z[jq * 4 + 1]);
                z[jq * 4 + 2] = fmaf(ov, w.z, z[jq * 4 + 2]);
                z[jq * 4 + 3] = fmaf(ov, w.w, z[jq * 4 + 3]);
            }
        }
#pragma unroll
        for (int j = 0; j < 16; j++)
            acc2 = fmaf(gelu_exact(z[j]), sm[O_MW2 + jc * 16 + j], acc2);
    }
    const float m = gelu_exact(acc2 + sm[O_MB2]);

    float4* dst = reinterpret_cast<float4*>(g_oflat + (size_t)tok * MD + i * 16);
#pragma unroll
    for (int dq = 0; dq < 4; dq++)
        dst[dq] = make_float4(tf32_rna(o2[dq * 4 + 0] + m), tf32_rna(o2[dq * 4 + 1] + m),
                              tf32_rna(o2[dq * 4 + 2] + m), tf32_rna(o2[dq * 4 + 3] + m));
}

// ---------------------------------------------------------------------------
// K3 (fused, RNA-tf32 operands staged via cp.async, double-buffered).
// ---------------------------------------------------------------------------
__device__ __forceinline__ void mma_tf32(float* c, const uint32_t* a, const uint32_t* bb) {
    asm volatile(
        "mma.sync.aligned.m16n8k8.row.col.f32.tf32.tf32.f32 "
        "{%0,%1,%2,%3}, {%4,%5,%6,%7}, {%8,%9}, {%0,%1,%2,%3};"
        : "+f"(c[0]), "+f"(c[1]), "+f"(c[2]), "+f"(c[3])
        : "r"(a[0]), "r"(a[1]), "r"(a[2]), "r"(a[3]), "r"(bb[0]), "r"(bb[1]));
}

constexpr int APAD = 36;
constexpr int BPAD = 72;
constexpr int CPAD = 66;
constexpr int BUFU = 128 * APAD + 32 * BPAD;       // 6912 floats per buffer
constexpr int FUSED_SMEM = 2 * BUFU * 4;           // 55296 B

__global__ __launch_bounds__(256) void fused_mlp_kernel(
    const float* __restrict__ b1, const float* __restrict__ W2) {
    extern __shared__ __align__(16) uint32_t smem_u[];
    float* Cs  = reinterpret_cast<float*>(smem_u);
    float* W2s = reinterpret_cast<float*>(smem_u) + 128 * CPAD;
    const uint32_t smem_base = (uint32_t)__cvta_generic_to_shared(smem_u);

    const int tid  = threadIdx.x;
    const int lane = tid & 31;
    const int wid  = tid >> 5;
    const int warp_m = wid & 3;
    const int warp_n = wid >> 2;
    const int row0 = blockIdx.x * 128;
    const int cg   = blockIdx.y;

    const int a_row  = tid >> 1;
    const int a_kofs = (tid & 1) * 16;
    const int b_krow = tid >> 3;
    const int b_ncol = (tid & 7) * 8;
    const int p2row = tid >> 1;
    const int p2n   = (tid & 1) * 8;

    const float* arow_g = g_oflat + (size_t)(row0 + a_row) * MD + a_kofs;
    const uint32_t a_dst = (uint32_t)(a_row * APAD + a_kofs) * 4u;
    const uint32_t b_dst = (uint32_t)(128 * APAD + b_krow * BPAD + b_ncol) * 4u;

    float out_acc[8];
#pragma unroll
    for (int i = 0; i < 8; i++) out_acc[i] = 0.f;

    for (int ch = cg * 2; ch < cg * 2 + 2; ch++) {
        const int col0 = ch * 64;
        const float* brow_g = g_w1r + (size_t)b_krow * FF + col0 + b_ncol;
        float cfr[2][4][4];
#pragma unroll
        for (int ma = 0; ma < 2; ma++)
#pragma unroll
            for (int na = 0; na < 4; na++)
#pragma unroll
                for (int i = 0; i < 4; i++) cfr[ma][na][i] = 0.f;

        {
            const uint32_t base = smem_base;
#pragma unroll
            for (int q = 0; q < 4; q++)
                cp_async16(base + a_dst + q * 16, arow_g + q * 4);
#pragma unroll
            for (int q = 0; q < 2; q++)
                cp_async16(base + b_dst + q * 16, brow_g + q * 4);
            cp_commit();
        }

#pragma unroll 1
        for (int kt = 0; kt < 8; kt++) {
            __syncthreads();
            if (kt < 7) {
                const uint32_t base = smem_base + (uint32_t)(((kt + 1) & 1) * BUFU) * 4u;
                const float* ag = arow_g + (kt + 1) * 32;
                const float* bg = brow_g + (size_t)(kt + 1) * 32 * FF;
#pragma unroll
                for (int q = 0; q < 4; q++)
                    cp_async16(base + a_dst + q * 16, ag + q * 4);
#pragma unroll
                for (int q = 0; q < 2; q++)
                    cp_async16(base + b_dst + q * 16, bg + q * 4);
            }
            cp_commit();
            cp_wait1();
            __syncthreads();

            const uint32_t* As = smem_u + (kt & 1) * BUFU;
            const uint32_t* Bs = As + 128 * APAD;
#pragma unroll
            for (int ks = 0; ks < 4; ks++) {
                const int k0 = ks * 8;
                uint32_t afr[2][4];
#pragma unroll
                for (int ma = 0; ma < 2; ma++) {
                    const int r = warp_m * 32 + ma * 16 + (lane >> 2);
                    const int kc = k0 + (lane & 3);
                    afr[ma][0] = As[r * APAD + kc];
                    afr[ma][1] = As[(r + 8) * APAD + kc];
                    afr[ma][2] = As[r * APAD + kc + 4];
                    afr[ma][3] = As[(r + 8) * APAD + kc + 4];
                }
                uint32_t bfr[4][2];
#pragma unroll
                for (int na = 0; na < 4; na++) {
                    const int n = warp_n * 32 + na * 8 + (lane >> 2);
                    const int kc = k0 + (lane & 3);
                    bfr[na][0] = Bs[kc * BPAD + n];
                    bfr[na][1] = Bs[(kc + 4) * BPAD + n];
                }
#pragma unroll
                for (int ma = 0; ma < 2; ma++)
#pragma unroll
                    for (int na = 0; na < 4; na++)
                        mma_tf32(cfr[ma][na], afr[ma], bfr[na]);
            }
        }

        __syncthreads();

#pragma unroll
        for (int ma = 0; ma < 2; ma++) {
            const int r0 = warp_m * 32 + ma * 16 + (lane >> 2);
#pragma unroll
            for (int na = 0; na < 4; na++) {
                const int cl = warp_n * 32 + na * 8 + 2 * (lane & 3);
                const float bb0 = __ldg(b1 + col0 + cl);
                const float bb1 = __ldg(b1 + col0 + cl + 1);
                float2 v0, v1;
                v0.x = gelu_exact(cfr[ma][na][0] + bb0);
                v0.y = gelu_exact(cfr[ma][na][1] + bb1);
                v1.x = gelu_exact(cfr[ma][na][2] + bb0);
                v1.y = gelu_exact(cfr[ma][na][3] + bb1);
                *reinterpret_cast<float2*>(&Cs[r0 * CPAD + cl]) = v0;
                *reinterpret_cast<float2*>(&Cs[(r0 + 8) * CPAD + cl]) = v1;
            }
        }
        *reinterpret_cast<float4*>(&W2s[(tid >> 2) * 16 + (tid & 3) * 4]) =
            *reinterpret_cast<const float4*>(W2 + (size_t)(col0 + (tid >> 2)) * 16 + (tid & 3) * 4);
        __syncthreads();

#pragma unroll 8
        for (int c = 0; c < 64; c++) {
            const float cv = Cs[p2row * CPAD + c];
            const float4 wa = *reinterpret_cast<const float4*>(&W2s[c * 16 + p2n]);
            const float4 wb = *reinterpret_cast<const float4*>(&W2s[c * 16 + p2n + 4]);
            out_acc[0] = fmaf(cv, wa.x, out_acc[0]);
            out_acc[1] = fmaf(cv, wa.y, out_acc[1]);
            out_acc[2] = fmaf(cv, wa.z, out_acc[2]);
            out_acc[3] = fmaf(cv, wa.w, out_acc[3]);
            out_acc[4] = fmaf(cv, wb.x, out_acc[4]);
            out_acc[5] = fmaf(cv, wb.y, out_acc[5]);
            out_acc[6] = fmaf(cv, wb.z, out_acc[6]);
            out_acc[7] = fmaf(cv, wb.w, out_acc[7]);
        }
        __syncthreads();
    }

    float* prow = &g_partial[cg][(size_t)(row0 + p2row) * OUT + p2n];
    *reinterpret_cast<float4*>(prow)     = make_float4(out_acc[0], out_acc[1], out_acc[2], out_acc[3]);
    *reinterpret_cast<float4*>(prow + 4) = make_float4(out_acc[4], out_acc[5], out_acc[6], out_acc[7]);
}

// ---------------------------------------------------------------------------
// K4: out = gelu(sum_cg partial + b2). Fixed summation order -> deterministic.
// ---------------------------------------------------------------------------
__global__ __launch_bounds__(256) void out_reduce(const float* __restrict__ b2,
                                                  float* __restrict__ out) {
    const int gid = blockIdx.x * 256 + threadIdx.x;
    const int n = gid & (OUT - 1);
    float s = g_partial[0][gid];
#pragma unroll
    for (int cg = 1; cg < NCG; cg++) s += g_partial[cg][gid];
    out[gid] = gelu_exact(s + b2[n]);
}

// ---------------------------------------------------------------------------
extern "C" void kernel_launch(void* const* d_in, const int* in_sizes, int n_in,
                              void* d_out, int out_size) {
    const float* x      = (const float*)d_in[0];
    const float* ct     = (const float*)d_in[1];
    const float* cs     = (const float*)d_in[2];
    const float* pe_w1  = (const float*)d_in[3];
    const float* pe_b1  = (const float*)d_in[4];
    const float* pe_w2  = (const float*)d_in[5];
    const float* pe_b2  = (const float*)d_in[6];
    const float* ln_g   = (const float*)d_in[7];
    const float* ln_b   = (const float*)d_in[8];
    const float* q_w    = (const float*)d_in[9];
    const float* k_w    = (const float*)d_in[10];
    const float* v_w    = (const float*)d_in[11];
    const float* ls     = (const float*)d_in[12];
    const float* out_w  = (const float*)d_in[13];
    const float* mnh_w1 = (const float*)d_in[14];
    const float* mnh_b1 = (const float*)d_in[15];
    const float* mnh_w2 = (const float*)d_in[16];
    const float* mnh_b2 = (const float*)d_in[17];
    const float* mo_w1  = (const float*)d_in[18];
    const float* mo_b1  = (const float*)d_in[19];
    const float* mo_w2  = (const float*)d_in[20];
    const float* mo_b2  = (const float*)d_in[21];

    cudaFuncSetAttribute(fused_mlp_kernel,
                         cudaFuncAttributeMaxDynamicSharedMemorySize, FUSED_SMEM);

    w1_round<<<MD * FF / 256, 256>>>(mo_w1);
    grid_build<<<B, 256>>>(cs);
    grid_build_t<<<B, 256>>>(ct);
    knn_kernel<<<dim3(T / 32, B), 256>>>();
    token_kernel<<<NTOK / 16, 256>>>(x, ct, cs, pe_w1, pe_b1, pe_w2, pe_b2,
                                     ln_g, ln_b, q_w, k_w, v_w, ls, out_w,
                                     mnh_w1, mnh_b1, mnh_w2, mnh_b2);
    fused_mlp_kernel<<<dim3(NTOK / 128, NCG), 256, FUSED_SMEM>>>(mo_b1, mo_w2);
    out_reduce<<<NTOK * OUT / 256, 256>>>(mo_b2, (float*)d_out);
}

// round 17
// speedup vs baseline: 1.3082x; 1.0924x over previous
#include <cuda_runtime.h>
#include <math.h>
#include <stdint.h>

constexpr int B = 4, T = 4096, S = 4096, E = 16;
constexpr int NH = 16, H = 4, FFNH = 64;
constexpr int MD = 256, FF = 1024, OUT = 16;
constexpr int NTOK = B * T;
constexpr int GC = 16;                 // knn grid cells per axis
constexpr int NCG = 8;                 // fused-MLP column groups

// Scratch (static device allocations — no cudaMalloc allowed)
__device__ int    g_idx[NTOK * NH];                // 1 MB
__device__ float  g_o2[(size_t)NTOK * MD];         // 16.8 MB (raw o2)
__device__ float  g_oflat[(size_t)NTOK * MD];      // 16.8 MB (RNA-tf32 values)
__device__ float  g_w1r[MD * FF];                  // 1 MB  (RNA-tf32 W1)
__device__ float2 g_gxy[B][S];
__device__ int    g_gid[B][S];
__device__ int    g_cstart[B][GC * GC + 1];
__device__ float2 g_txy[B][T];                     // spatially-sorted targets
__device__ int    g_tid_[B][T];
__device__ float  g_partial[NCG][(size_t)NTOK * OUT];

__device__ __forceinline__ float gelu_exact(float x) {
    return 0.5f * x * (1.0f + erff(x * 0.70710678118654752f));
}

__device__ __forceinline__ float tf32_rna(float f) {
    uint32_t u;
    asm("cvt.rna.tf32.f32 %0, %1;" : "=r"(u) : "f"(f));
    return __uint_as_float(u);
}

__device__ __forceinline__ void cp_async16(uint32_t dst, const void* src) {
    asm volatile("cp.async.cg.shared.global [%0], [%1], 16;\n" :: "r"(dst), "l"(src));
}
__device__ __forceinline__ void cp_commit() {
    asm volatile("cp.async.commit_group;\n" ::);
}
__device__ __forceinline__ void cp_wait1() {
    asm volatile("cp.async.wait_group 1;\n" ::);
}

// ---------------------------------------------------------------------------
// K-1: pre-round W1 to RNA tf32.
// ---------------------------------------------------------------------------
__global__ __launch_bounds__(256) void w1_round(const float* __restrict__ W1) {
    const int i = blockIdx.x * 256 + threadIdx.x;
    g_w1r[i] = tf32_rna(W1[i]);
}

// ---------------------------------------------------------------------------
// K0a/K0b: counting-sort sources AND targets into the 16x16 grid.
// ---------------------------------------------------------------------------
__global__ __launch_bounds__(256) void grid_build(const float* __restrict__ cs) {
    __shared__ int cnt[GC * GC];
    __shared__ int start[GC * GC + 1];
    const int b = blockIdx.x, tid = threadIdx.x;
    cnt[tid] = 0;
    __syncthreads();
    const float2* csb = reinterpret_cast<const float2*>(cs) + (size_t)b * S;
    for (int i = tid; i < S; i += 256) {
        float2 c = csb[i];
        int cx = min(GC - 1, (int)(c.x * GC));
        int cy = min(GC - 1, (int)(c.y * GC));
        atomicAdd(&cnt[cy * GC + cx], 1);
    }
    __syncthreads();
    if (tid == 0) {
        int acc = 0;
        for (int i = 0; i < GC * GC; i++) { start[i] = acc; acc += cnt[i]; }
        start[GC * GC] = acc;
    }
    __syncthreads();
    cnt[tid] = start[tid];
    g_cstart[b][tid] = start[tid];
    if (tid == 0) g_cstart[b][GC * GC] = start[GC * GC];
    __syncthreads();
    for (int i = tid; i < S; i += 256) {
        float2 c = csb[i];
        int cx = min(GC - 1, (int)(c.x * GC));
        int cy = min(GC - 1, (int)(c.y * GC));
        int pos = atomicAdd(&cnt[cy * GC + cx], 1);
        g_gxy[b][pos] = c;
        g_gid[b][pos] = i;
    }
}

__global__ __launch_bounds__(256) void grid_build_t(const float* __restrict__ ct) {
    __shared__ int cnt[GC * GC];
    __shared__ int start[GC * GC + 1];
    const int b = blockIdx.x, tid = threadIdx.x;
    cnt[tid] = 0;
    __syncthreads();
    const float2* ctb = reinterpret_cast<const float2*>(ct) + (size_t)b * T;
    for (int i = tid; i < T; i += 256) {
        float2 c = ctb[i];
        int cx = min(GC - 1, (int)(c.x * GC));
        int cy = min(GC - 1, (int)(c.y * GC));
        atomicAdd(&cnt[cy * GC + cx], 1);
    }
    __syncthreads();
    if (tid == 0) {
        int acc = 0;
        for (int i = 0; i < GC * GC; i++) { start[i] = acc; acc += cnt[i]; }
        start[GC * GC] = acc;
    }
    __syncthreads();
    cnt[tid] = start[tid];
    __syncthreads();
    for (int i = tid; i < T; i += 256) {
        float2 c = ctb[i];
        int cx = min(GC - 1, (int)(c.x * GC));
        int cy = min(GC - 1, (int)(c.y * GC));
        int pos = atomicAdd(&cnt[cy * GC + cx], 1);
        g_txy[b][pos] = c;
        g_tid_[b][pos] = i;
    }
}

// ---------------------------------------------------------------------------
// K1: exact 16-NN, spatially-sorted targets, FOUR lanes per target.
// All lanes walk the same cells; points split j += 4 (balanced). Merge:
// 2 bitonic set-merge stages (xor1, xor2). u64 keys -> order-invariant.
// ---------------------------------------------------------------------------
__device__ __forceinline__ void key_insert(unsigned long long* key,
                                           unsigned long long ck) {
    if (ck < key[NH - 1]) {
        bool ins = false;
#pragma unroll
        for (int q = 0; q < NH; q++) {
            bool sm = ins | (ck < key[q]);
            unsigned long long tk = key[q];
            key[q] = sm ? ck : tk;
            ck = sm ? tk : ck;
            ins = sm;
        }
    }
}

__global__ __launch_bounds__(256) void knn_kernel() {
    const int b = blockIdx.y;
    const int lane = threadIdx.x & 31;
    const int sub = threadIdx.x & 3;                     // point-split class
    const unsigned quadmask = 0xFu << (lane & ~3);
    const int s = blockIdx.x * 64 + (threadIdx.x >> 2);  // sorted target slot
    const float2 tc = g_txy[b][s];
    const int torig = g_tid_[b][s];
    const float tx = tc.x, ty = tc.y;
    const int cx = min(GC - 1, (int)(tx * GC));
    const int cy = min(GC - 1, (int)(ty * GC));

    const float2* __restrict__ gxy = g_gxy[b];
    const int*    __restrict__ gid = g_gid[b];
    const int*    __restrict__ cst = g_cstart[b];
    constexpr float hcell = 1.0f / GC;
    constexpr unsigned long long KMAX = 0xFFFFFFFFFFFFFFFFull;

    unsigned long long key[NH];
#pragma unroll
    for (int i = 0; i < NH; i++) key[i] = KMAX;

    for (int rho = 0; rho <= GC - 1; rho++) {
        if (rho > 1) {
            // min of local worsts over the quad: upper-bounds union's 16th.
            float wl = __uint_as_float((unsigned)(key[NH - 1] >> 32));
            wl = fminf(wl, __shfl_xor_sync(quadmask, wl, 1));
            wl = fminf(wl, __shfl_xor_sync(quadmask, wl, 2));
            const float bound = (rho - 1) * hcell;
            if (wl < bound * bound) break;               // uniform across quad
        }
        const int ylo = max(cy - rho, 0), yhi = min(cy + rho, GC - 1);
        for (int ay = ylo; ay <= yhi; ay++) {
            const bool fullrow = (ay == cy - rho) || (ay == cy + rho);
            const int step = fullrow ? 1 : (rho > 0 ? 2 * rho : 1);
            for (int ax = cx - rho; ax <= cx + rho; ax += step) {
                if (ax < 0 || ax >= GC) continue;
                const int cell = ay * GC + ax;
                const int c1 = cst[cell + 1];
                for (int j = cst[cell] + sub; j < c1; j += 4) {
                    const float2 p = gxy[j];
                    const float dxx = tx - p.x, dyy = ty - p.y;
                    const float d2 = fmaf(dyy, dyy, dxx * dxx);
                    unsigned long long ck =
                        ((unsigned long long)__float_as_uint(d2) << 32) |
                        (unsigned)gid[j];
                    key_insert(key, ck);
                }
            }
        }
    }

    // 2 merge stages (xor1, xor2): t[i]=min(A[i],B[15-i]) = 16 smallest of
    // union (bitonic), then half-cleaner sort. Shuffle reads current regs,
    // writes land in t -> race-free; symmetric merge keeps lanes identical.
#pragma unroll
    for (int st = 0; st < 2; st++) {
        const int d = 1 << st;
        unsigned long long t[NH];
#pragma unroll
        for (int i = 0; i < NH; i++) {
            unsigned long long other = __shfl_xor_sync(quadmask, key[NH - 1 - i], d);
            t[i] = key[i] < other ? key[i] : other;
        }
#pragma unroll
        for (int dd = 8; dd >= 1; dd >>= 1) {
#pragma unroll
            for (int i = 0; i < NH; i++) {
                if (!(i & dd)) {
                    unsigned long long a = t[i], bb = t[i | dd];
                    t[i]      = a < bb ? a : bb;
                    t[i | dd] = a < bb ? bb : a;
                }
            }
        }
#pragma unroll
        for (int i = 0; i < NH; i++) key[i] = t[i];
    }

    if (sub == 0) {
        const int base = (b * T + torig) * NH;
#pragma unroll
        for (int i = 0; i < NH; i++)
            g_idx[base + i] = (int)(key[i] & 0xFFFFFFFFull);
    }
}

// ---------------------------------------------------------------------------
// K2a: per-token pipeline through attention out-projection; writes raw o2.
// (mnh MLP moved to K2b for occupancy; FP order unchanged.)
// ---------------------------------------------------------------------------
constexpr int O_PEW1 = 0;
constexpr int O_PEB1 = 128;
constexpr int O_PEW2 = 192;
constexpr int O_PEB2 = 1216;
constexpr int O_LNG  = 1232;
constexpr int O_LNB  = 1248;
constexpr int O_QW   = 1264;
constexpr int O_KW   = 1520;
constexpr int O_VW   = 1776;
constexpr int O_OW   = 2032;
constexpr int O_SC   = 2288;
constexpr int O_KV   = 2292;
constexpr int SM_TOT = 2292 + 16 * 132;

__device__ __forceinline__ void mat16(const float* __restrict__ Wsh,
                                      const float* __restrict__ vin,
                                      float* __restrict__ vout) {
#pragma unroll
    for (int k = 0; k < 16; k++) {
        const float hv = vin[k];
#pragma unroll
        for (int dq = 0; dq < 4; dq++) {
            float4 w = *reinterpret_cast<const float4*>(Wsh + k * 16 + dq * 4);
            vout[dq * 4 + 0] = fmaf(hv, w.x, vout[dq * 4 + 0]);
            vout[dq * 4 + 1] = fmaf(hv, w.y, vout[dq * 4 + 1]);
            vout[dq * 4 + 2] = fmaf(hv, w.z, vout[dq * 4 + 2]);
            vout[dq * 4 + 3] = fmaf(hv, w.w, vout[dq * 4 + 3]);
        }
    }
}

__global__ __launch_bounds__(256, 3) void token_kernel(
    const float* __restrict__ x, const float* __restrict__ ct, const float* __restrict__ cs,
    const float* __restrict__ pe_w1, const float* __restrict__ pe_b1,
    const float* __restrict__ pe_w2, const float* __restrict__ pe_b2,
    const float* __restrict__ ln_g, const float* __restrict__ ln_b,
    const float* __restrict__ q_w, const float* __restrict__ k_w,
    const float* __restrict__ v_w, const float* __restrict__ lscale,
    const float* __restrict__ out_w) {
    __shared__ float sm[SM_TOT];
    const int tid = threadIdx.x;
    for (int i = tid; i < 128;  i += 256) sm[O_PEW1 + i] = pe_w1[i];
    for (int i = tid; i < 64;   i += 256) sm[O_PEB1 + i] = pe_b1[i];
    for (int i = tid; i < 1024; i += 256) sm[O_PEW2 + i] = pe_w2[i];
    for (int i = tid; i < 16;   i += 256) sm[O_PEB2 + i] = pe_b2[i];
    for (int i = tid; i < 16;   i += 256) sm[O_LNG + i]  = ln_g[i];
    for (int i = tid; i < 16;   i += 256) sm[O_LNB + i]  = ln_b[i];
    for (int i = tid; i < 256;  i += 256) sm[O_QW + i]   = q_w[i];
    for (int i = tid; i < 256;  i += 256) sm[O_KW + i]   = k_w[i];
    for (int i = tid; i < 256;  i += 256) sm[O_VW + i]   = v_w[i];
    for (int i = tid; i < 256;  i += 256) sm[O_OW + i]   = out_w[i];
    if (tid < 4)  sm[O_SC + tid] = expf(fminf(lscale[tid], 4.6051702f));
    __syncthreads();

    const int tok = blockIdx.x * 16 + (tid >> 4);
    const int g   = tid >> 4;
    const int i   = tid & 15;
    const int b   = tok / T;
    const int nidx = g_idx[tok * NH + i];

    float xr[16];
    const float4* xrow = reinterpret_cast<const float4*>(x + ((size_t)b * S + nidx) * E);
#pragma unroll
    for (int q4 = 0; q4 < 4; q4++) {
        float4 v4 = __ldg(xrow + q4);
        xr[q4 * 4 + 0] = v4.x; xr[q4 * 4 + 1] = v4.y;
        xr[q4 * 4 + 2] = v4.z; xr[q4 * 4 + 3] = v4.w;
    }
    const float2 scoord = __ldg(reinterpret_cast<const float2*>(cs) + (size_t)b * S + nidx);
    const float2 tcoord = __ldg(reinterpret_cast<const float2*>(ct) + tok);
    const float c0 = scoord.x - tcoord.x, c1 = scoord.y - tcoord.y;

    float h[16];
#pragma unroll
    for (int d = 0; d < 16; d++) h[d] = sm[O_PEB2 + d];
#pragma unroll
    for (int j4 = 0; j4 < FFNH; j4 += 4) {
        const float4 wa = *reinterpret_cast<const float4*>(sm + O_PEW1 + j4);
        const float4 wb = *reinterpret_cast<const float4*>(sm + O_PEW1 + 64 + j4);
        const float4 bb = *reinterpret_cast<const float4*>(sm + O_PEB1 + j4);
        float zq[4];
        zq[0] = fmaf(c0, wa.x, fmaf(c1, wb.x, bb.x));
        zq[1] = fmaf(c0, wa.y, fmaf(c1, wb.y, bb.y));
        zq[2] = fmaf(c0, wa.z, fmaf(c1, wb.z, bb.z));
        zq[3] = fmaf(c0, wa.w, fmaf(c1, wb.w, bb.w));
#pragma unroll
        for (int ss = 0; ss < 4; ss++) {
            const float z = gelu_exact(zq[ss]);
            const int j = j4 + ss;
#pragma unroll
            for (int dq = 0; dq < 4; dq++) {
                float4 w = *reinterpret_cast<const float4*>(sm + O_PEW2 + j * 16 + dq * 4);
                h[dq * 4 + 0] = fmaf(z, w.x, h[dq * 4 + 0]);
                h[dq * 4 + 1] = fmaf(z, w.y, h[dq * 4 + 1]);
                h[dq * 4 + 2] = fmaf(z, w.z, h[dq * 4 + 2]);
                h[dq * 4 + 3] = fmaf(z, w.w, h[dq * 4 + 3]);
            }
        }
    }

    float mu = 0.f;
#pragma unroll
    for (int d = 0; d < 16; d++) { h[d] += xr[d]; mu += h[d]; }
    mu *= (1.f / 16.f);
    float var = 0.f;
#pragma unroll
    for (int d = 0; d < 16; d++) { float c = h[d] - mu; var = fmaf(c, c, var); }
    var *= (1.f / 16.f);
    const float rstd = 1.f / sqrtf(var + 1e-5f);
#pragma unroll
    for (int d = 0; d < 16; d++)
        h[d] = (h[d] - mu) * rstd * sm[O_LNG + d] + sm[O_LNB + d];

    float q[16], k[16], v[16];
#pragma unroll
    for (int d = 0; d < 16; d++) { q[d] = 0.f; k[d] = 0.f; v[d] = 0.f; }
    mat16(sm + O_QW, h, q);
    mat16(sm + O_KW, h, k);
    mat16(sm + O_VW, xr, v);

    float4* myslot = reinterpret_cast<float4*>(sm + O_KV + g * 132 + i * 8);
    float o[16];
#pragma unroll
    for (int hh = 0; hh < H; hh++) {
        float qh[4], kh[4], vh[4];
#pragma unroll
        for (int c = 0; c < 4; c++) {
            qh[c] = q[hh * 4 + c]; kh[c] = k[hh * 4 + c]; vh[c] = v[hh * 4 + c];
        }
        float qs = fmaf(qh[3], qh[3], fmaf(qh[2], qh[2], fmaf(qh[1], qh[1], qh[0] * qh[0])));
        float ks = fmaf(kh[3], kh[3], fmaf(kh[2], kh[2], fmaf(kh[1], kh[1], kh[0] * kh[0])));
        const float qi = 1.f / (sqrtf(qs) + 1e-6f);
        const float ki = 1.f / (sqrtf(ks) + 1e-6f);
#pragma unroll
        for (int c = 0; c < 4; c++) { qh[c] *= qi; kh[c] *= ki; }

        __syncwarp();
        myslot[0] = make_float4(kh[0], kh[1], kh[2], kh[3]);
        myslot[1] = make_float4(vh[0], vh[1], vh[2], vh[3]);
        __syncwarp();

        const float scl = sm[O_SC + hh];
        float lg[16];
#pragma unroll
        for (int j = 0; j < 16; j++) {
            const float4 kj = *reinterpret_cast<const float4*>(sm + O_KV + g * 132 + j * 8);
            float dot = 0.f;
            dot = fmaf(qh[0], kj.x, dot);
            dot = fmaf(qh[1], kj.y, dot);
            dot = fmaf(qh[2], kj.z, dot);
            dot = fmaf(qh[3], kj.w, dot);
            lg[j] = dot * scl;
        }
        float mx = lg[0];
#pragma unroll
        for (int j = 1; j < 16; j++) mx = fmaxf(mx, lg[j]);
        float ssum = 0.f;
#pragma unroll
        for (int j = 0; j < 16; j++) { lg[j] = expf(lg[j] - mx); ssum += lg[j]; }
        const float inv = 1.f / ssum;
        float oh[4] = {0.f, 0.f, 0.f, 0.f};
#pragma unroll
        for (int j = 0; j < 16; j++) {
            const float a = lg[j] * inv;
            const float4 vj = *reinterpret_cast<const float4*>(sm + O_KV + g * 132 + j * 8 + 4);
            oh[0] = fmaf(a, vj.x, oh[0]);
            oh[1] = fmaf(a, vj.y, oh[1]);
            oh[2] = fmaf(a, vj.z, oh[2]);
            oh[3] = fmaf(a, vj.w, oh[3]);
        }
#pragma unroll
        for (int c = 0; c < 4; c++) o[hh * 4 + c] = oh[c];
    }

    float o2[16];
#pragma unroll
    for (int d = 0; d < 16; d++) o2[d] = 0.f;
    mat16(sm + O_OW, o, o2);

    float4* dst = reinterpret_cast<float4*>(g_o2 + (size_t)tok * MD + i * 16);
#pragma unroll
    for (int dq = 0; dq < 4; dq++)
        dst[dq] = make_float4(o2[dq * 4 + 0], o2[dq * 4 + 1],
                              o2[dq * 4 + 2], o2[dq * 4 + 3]);
}

// ---------------------------------------------------------------------------
// K2b: per-neighbor MLP + broadcast residual + tf32 store. One thread per
// (token, neighbor); low regs -> high occupancy. Same FP order as before.
// ---------------------------------------------------------------------------
constexpr int M_MW1 = 0;       // 1024
constexpr int M_MB1 = 1024;    // 64
constexpr int M_MW2 = 1088;    // 64
constexpr int M_MB2 = 1152;    // 1
constexpr int M_TOT = 1156;

__global__ __launch_bounds__(256) void mnh_kernel(
    const float* __restrict__ mnh_w1, const float* __restrict__ mnh_b1,
    const float* __restrict__ mnh_w2, const float* __restrict__ mnh_b2) {
    __shared__ float sm[M_TOT];
    const int tid = threadIdx.x;
    for (int i = tid; i < 1024; i += 256) sm[M_MW1 + i] = mnh_w1[i];
    for (int i = tid; i < 64;   i += 256) sm[M_MB1 + i] = mnh_b1[i];
    for (int i = tid; i < 64;   i += 256) sm[M_MW2 + i] = mnh_w2[i];
    if (tid == 0) sm[M_MB2] = mnh_b2[0];
    __syncthreads();

    const int slot = blockIdx.x * 256 + tid;          // (tok*16 + i)
    float o2[16];
    const float4* src = reinterpret_cast<const float4*>(g_o2 + (size_t)slot * 16);
#pragma unroll
    for (int dq = 0; dq < 4; dq++) {
        float4 v4 = src[dq];
        o2[dq * 4 + 0] = v4.x; o2[dq * 4 + 1] = v4.y;
        o2[dq * 4 + 2] = v4.z; o2[dq * 4 + 3] = v4.w;
    }

    float acc2 = 0.f;
#pragma unroll
    for (int jc = 0; jc < 4; jc++) {
        float z[16];
#pragma unroll
        for (int jq = 0; jq < 4; jq++) {
            const float4 bb = *reinterpret_cast<const float4*>(sm + M_MB1 + jc * 16 + jq * 4);
            z[jq * 4 + 0] = bb.x; z[jq * 4 + 1] = bb.y;
            z[jq * 4 + 2] = bb.z; z[jq * 4 + 3] = bb.w;
        }
#pragma unroll
        for (int kk = 0; kk < 16; kk++) {
            const float ov = o2[kk];
#pragma unroll
            for (int jq = 0; jq < 4; jq++) {
                const float4 w = *reinterpret_cast<const float4*>(
                    sm + M_MW1 + kk * 64 + jc * 16 + jq * 4);
                z[jq * 4 + 0] = fmaf(ov, w.x, z[jq * 4 + 0]);
                z[jq * 4 + 1] = fmaf(ov, w.y, z[jq * 4 + 1]);
                z[jq * 4 + 2] = fmaf(ov, w.z, z[jq * 4 + 2]);
                z[jq * 4 + 3] = fmaf(ov, w.w, z[jq * 4 + 3]);
            }
        }
#pragma unroll
        for (int j = 0; j < 16; j++)
            acc2 = fmaf(gelu_exact(z[j]), sm[M_MW2 + jc * 16 + j], acc2);
    }
    const float m = gelu_exact(acc2 + sm[M_MB2]);

    float4* dst = reinterpret_cast<float4*>(g_oflat + (size_t)slot * 16);
#pragma unroll
    for (int dq = 0; dq < 4; dq++)
        dst[dq] = make_float4(tf32_rna(o2[dq * 4 + 0] + m), tf32_rna(o2[dq * 4 + 1] + m),
                              tf32_rna(o2[dq * 4 + 2] + m), tf32_rna(o2[dq * 4 + 3] + m));
}

// ---------------------------------------------------------------------------
// K3 (fused, RNA-tf32 operands staged via cp.async, double-buffered).
// ---------------------------------------------------------------------------
__device__ __forceinline__ void mma_tf32(float* c, const uint32_t* a, const uint32_t* bb) {
    asm volatile(
        "mma.sync.aligned.m16n8k8.row.col.f32.tf32.tf32.f32 "
        "{%0,%1,%2,%3}, {%4,%5,%6,%7}, {%8,%9}, {%0,%1,%2,%3};"
        : "+f"(c[0]), "+f"(c[1]), "+f"(c[2]), "+f"(c[3])
        : "r"(a[0]), "r"(a[1]), "r"(a[2]), "r"(a[3]), "r"(bb[0]), "r"(bb[1]));
}

constexpr int APAD = 36;
constexpr int BPAD = 72;
constexpr int CPAD = 66;
constexpr int BUFU = 128 * APAD + 32 * BPAD;       // 6912 floats per buffer
constexpr int FUSED_SMEM = 2 * BUFU * 4;           // 55296 B

__global__ __launch_bounds__(256) void fused_mlp_kernel(
    const float* __restrict__ b1, const float* __restrict__ W2) {
    extern __shared__ __align__(16) uint32_t smem_u[];
    float* Cs  = reinterpret_cast<float*>(smem_u);
    float* W2s = reinterpret_cast<float*>(smem_u) + 128 * CPAD;
    const uint32_t smem_base = (uint32_t)__cvta_generic_to_shared(smem_u);

    const int tid  = threadIdx.x;
    const int lane = tid & 31;
    const int wid  = tid >> 5;
    const int warp_m = wid & 3;
    const int warp_n = wid >> 2;
    const int row0 = blockIdx.x * 128;
    const int cg   = blockIdx.y;

    const int a_row  = tid >> 1;
    const int a_kofs = (tid & 1) * 16;
    const int b_krow = tid >> 3;
    const int b_ncol = (tid & 7) * 8;
    const int p2row = tid >> 1;
    const int p2n   = (tid & 1) * 8;

    const float* arow_g = g_oflat + (size_t)(row0 + a_row) * MD + a_kofs;
    const uint32_t a_dst = (uint32_t)(a_row * APAD + a_kofs) * 4u;
    const uint32_t b_dst = (uint32_t)(128 * APAD + b_krow * BPAD + b_ncol) * 4u;

    float out_acc[8];
#pragma unroll
    for (int i = 0; i < 8; i++) out_acc[i] = 0.f;

    for (int ch = cg * 2; ch < cg * 2 + 2; ch++) {
        const int col0 = ch * 64;
        const float* brow_g = g_w1r + (size_t)b_krow * FF + col0 + b_ncol;
        float cfr[2][4][4];
#pragma unroll
        for (int ma = 0; ma < 2; ma++)
#pragma unroll
            for (int na = 0; na < 4; na++)
#pragma unroll
                for (int i = 0; i < 4; i++) cfr[ma][na][i] = 0.f;

        {
            const uint32_t base = smem_base;
#pragma unroll
            for (int q = 0; q < 4; q++)
                cp_async16(base + a_dst + q * 16, arow_g + q * 4);
#pragma unroll
            for (int q = 0; q < 2; q++)
                cp_async16(base + b_dst + q * 16, brow_g + q * 4);
            cp_commit();
        }

#pragma unroll 1
        for (int kt = 0; kt < 8; kt++) {
            __syncthreads();
            if (kt < 7) {
                const uint32_t base = smem_base + (uint32_t)(((kt + 1) & 1) * BUFU) * 4u;
                const float* ag = arow_g + (kt + 1) * 32;
                const float* bg = brow_g + (size_t)(kt + 1) * 32 * FF;
#pragma unroll
                for (int q = 0; q < 4; q++)
                    cp_async16(base + a_dst + q * 16, ag + q * 4);
#pragma unroll
                for (int q = 0; q < 2; q++)
                    cp_async16(base + b_dst + q * 16, bg + q * 4);
            }
            cp_commit();
            cp_wait1();
            __syncthreads();

            const uint32_t* As = smem_u + (kt & 1) * BUFU;
            const uint32_t* Bs = As + 128 * APAD;
#pragma unroll
            for (int ks = 0; ks < 4; ks++) {
                const int k0 = ks * 8;
                uint32_t afr[2][4];
#pragma unroll
                for (int ma = 0; ma < 2; ma++) {
                    const int r = warp_m * 32 + ma * 16 + (lane >> 2);
                    const int kc = k0 + (lane & 3);
                    afr[ma][0] = As[r * APAD + kc];
                    afr[ma][1] = As[(r + 8) * APAD + kc];
                    afr[ma][2] = As[r * APAD + kc + 4];
                    afr[ma][3] = As[(r + 8) * APAD + kc + 4];
                }
                uint32_t bfr[4][2];
#pragma unroll
                for (int na = 0; na < 4; na++) {
                    const int n = warp_n * 32 + na * 8 + (lane >> 2);
                    const int kc = k0 + (lane & 3);
                    bfr[na][0] = Bs[kc * BPAD + n];
                    bfr[na][1] = Bs[(kc + 4) * BPAD + n];
                }
#pragma unroll
                for (int ma = 0; ma < 2; ma++)
#pragma unroll
                    for (int na = 0; na < 4; na++)
                        mma_tf32(cfr[ma][na], afr[ma], bfr[na]);
            }
        }

        __syncthreads();

#pragma unroll
        for (int ma = 0; ma < 2; ma++) {
            const int r0 = warp_m * 32 + ma * 16 + (lane >> 2);
#pragma unroll
            for (int na = 0; na < 4; na++) {
                const int cl = warp_n * 32 + na * 8 + 2 * (lane & 3);
                const float bb0 = __ldg(b1 + col0 + cl);
                const float bb1 = __ldg(b1 + col0 + cl + 1);
                float2 v0, v1;
                v0.x = gelu_exact(cfr[ma][na][0] + bb0);
                v0.y = gelu_exact(cfr[ma][na][1] + bb1);
                v1.x = gelu_exact(cfr[ma][na][2] + bb0);
                v1.y = gelu_exact(cfr[ma][na][3] + bb1);
                *reinterpret_cast<float2*>(&Cs[r0 * CPAD + cl]) = v0;
                *reinterpret_cast<float2*>(&Cs[(r0 + 8) * CPAD + cl]) = v1;
            }
        }
        *reinterpret_cast<float4*>(&W2s[(tid >> 2) * 16 + (tid & 3) * 4]) =
            *reinterpret_cast<const float4*>(W2 + (size_t)(col0 + (tid >> 2)) * 16 + (tid & 3) * 4);
        __syncthreads();

#pragma unroll 8
        for (int c = 0; c < 64; c++) {
            const float cv = Cs[p2row * CPAD + c];
            const float4 wa = *reinterpret_cast<const float4*>(&W2s[c * 16 + p2n]);
            const float4 wb = *reinterpret_cast<const float4*>(&W2s[c * 16 + p2n + 4]);
            out_acc[0] = fmaf(cv, wa.x, out_acc[0]);
            out_acc[1] = fmaf(cv, wa.y, out_acc[1]);
            out_acc[2] = fmaf(cv, wa.z, out_acc[2]);
            out_acc[3] = fmaf(cv, wa.w, out_acc[3]);
            out_acc[4] = fmaf(cv, wb.x, out_acc[4]);
            out_acc[5] = fmaf(cv, wb.y, out_acc[5]);
            out_acc[6] = fmaf(cv, wb.z, out_acc[6]);
            out_acc[7] = fmaf(cv, wb.w, out_acc[7]);
        }
        __syncthreads();
    }

    float* prow = &g_partial[cg][(size_t)(row0 + p2row) * OUT + p2n];
    *reinterpret_cast<float4*>(prow)     = make_float4(out_acc[0], out_acc[1], out_acc[2], out_acc[3]);
    *reinterpret_cast<float4*>(prow + 4) = make_float4(out_acc[4], out_acc[5], out_acc[6], out_acc[7]);
}

// ---------------------------------------------------------------------------
// K4: out = gelu(sum_cg partial + b2). Fixed summation order -> deterministic.
// ---------------------------------------------------------------------------
__global__ __launch_bounds__(256) void out_reduce(const float* __restrict__ b2,
                                                  float* __restrict__ out) {
    const int gid = blockIdx.x * 256 + threadIdx.x;
    const int n = gid & (OUT - 1);
    float s = g_partial[0][gid];
#pragma unroll
    for (int cg = 1; cg < NCG; cg++) s += g_partial[cg][gid];
    out[gid] = gelu_exact(s + b2[n]);
}

// ---------------------------------------------------------------------------
extern "C" void kernel_launch(void* const* d_in, const int* in_sizes, int n_in,
                              void* d_out, int out_size) {
    const float* x      = (const float*)d_in[0];
    const float* ct     = (const float*)d_in[1];
    const float* cs     = (const float*)d_in[2];
    const float* pe_w1  = (const float*)d_in[3];
    const float* pe_b1  = (const float*)d_in[4];
    const float* pe_w2  = (const float*)d_in[5];
    const float* pe_b2  = (const float*)d_in[6];
    const float* ln_g   = (const float*)d_in[7];
    const float* ln_b   = (const float*)d_in[8];
    const float* q_w    = (const float*)d_in[9];
    const float* k_w    = (const float*)d_in[10];
    const float* v_w    = (const float*)d_in[11];
    const float* ls     = (const float*)d_in[12];
    const float* out_w  = (const float*)d_in[13];
    const float* mnh_w1 = (const float*)d_in[14];
    const float* mnh_b1 = (const float*)d_in[15];
    const float* mnh_w2 = (const float*)d_in[16];
    const float* mnh_b2 = (const float*)d_in[17];
    const float* mo_w1  = (const float*)d_in[18];
    const float* mo_b1  = (const float*)d_in[19];
    const float* mo_w2  = (const float*)d_in[20];
    const float* mo_b2  = (const float*)d_in[21];

    cudaFuncSetAttribute(fused_mlp_kernel,
                         cudaFuncAttributeMaxDynamicSharedMemorySize, FUSED_SMEM);

    w1_round<<<MD * FF / 256, 256>>>(mo_w1);
    grid_build<<<B, 256>>>(cs);
    grid_build_t<<<B, 256>>>(ct);
    knn_kernel<<<dim3(T / 64, B), 256>>>();
    token_kernel<<<NTOK / 16, 256>>>(x, ct, cs, pe_w1, pe_b1, pe_w2, pe_b2,
                                     ln_g, ln_b, q_w, k_w, v_w, ls, out_w);
    mnh_kernel<<<NTOK * NH / 256, 256>>>(mnh_w1, mnh_b1, mnh_w2, mnh_b2);
    fused_mlp_kernel<<<dim3(NTOK / 128, NCG), 256, FUSED_SMEM>>>(mo_b1, mo_w2);
    out_reduce<<<NTOK * OUT / 256, 256>>>(mo_b2, (float*)d_out);
}